// round 1
// baseline (speedup 1.0000x reference)
#include <cuda_runtime.h>
#include <math.h>

// Problem constants
#define BB 4
#define LL 2048
#define EE 1024
#define HH 16
#define DD 64
#define ML (BB * LL)   // 8192 total rows

// Scratch (device globals: allocation-free per harness rules)
__device__ float g_q[ML * EE];
__device__ float g_k[ML * EE];
__device__ float g_v[ML * EE];
__device__ float g_ctx[ML * EE];

// ---------------------------------------------------------------------------
// SGEMM: C[M,N] = A[M,K] @ W[N,K]^T (+ bias[N])
// 128x128 block tile, K-tile 16, 256 threads, 8x8 per-thread microtile.
// ---------------------------------------------------------------------------
#define GTM 128
#define GTN 128
#define GTK 16
#define GPAD 4   // keeps rows 16B-aligned for float4 smem reads

__global__ __launch_bounds__(256) void sgemm_nt(const float* __restrict__ A,
                                                const float* __restrict__ W,
                                                const float* __restrict__ bias,
                                                float* __restrict__ C,
                                                int M, int N, int K) {
    __shared__ float As[GTK][GTM + GPAD];
    __shared__ float Ws[GTK][GTN + GPAD];

    const int tid = threadIdx.x;
    const int bm = blockIdx.x * GTM;
    const int bn = blockIdx.y * GTN;
    const int tx = tid & 15;
    const int ty = tid >> 4;
    const int lrow = tid >> 2;          // 0..63
    const int lcol = (tid & 3) << 2;    // 0,4,8,12

    float acc[8][8];
#pragma unroll
    for (int i = 0; i < 8; i++)
#pragma unroll
        for (int j = 0; j < 8; j++) acc[i][j] = 0.0f;

    for (int k0 = 0; k0 < K; k0 += GTK) {
#pragma unroll
        for (int hf = 0; hf < 2; hf++) {
            int r = lrow + hf * 64;
            float4 a = *(const float4*)(A + (size_t)(bm + r) * K + k0 + lcol);
            As[lcol + 0][r] = a.x;
            As[lcol + 1][r] = a.y;
            As[lcol + 2][r] = a.z;
            As[lcol + 3][r] = a.w;
            float4 w = *(const float4*)(W + (size_t)(bn + r) * K + k0 + lcol);
            Ws[lcol + 0][r] = w.x;
            Ws[lcol + 1][r] = w.y;
            Ws[lcol + 2][r] = w.z;
            Ws[lcol + 3][r] = w.w;
        }
        __syncthreads();

#pragma unroll
        for (int kk = 0; kk < GTK; kk++) {
            float4 a0 = *(const float4*)&As[kk][ty * 8];
            float4 a1 = *(const float4*)&As[kk][ty * 8 + 4];
            float4 w0 = *(const float4*)&Ws[kk][tx * 8];
            float4 w1 = *(const float4*)&Ws[kk][tx * 8 + 4];
            float av[8] = {a0.x, a0.y, a0.z, a0.w, a1.x, a1.y, a1.z, a1.w};
            float wv[8] = {w0.x, w0.y, w0.z, w0.w, w1.x, w1.y, w1.z, w1.w};
#pragma unroll
            for (int i = 0; i < 8; i++)
#pragma unroll
                for (int j = 0; j < 8; j++) acc[i][j] += av[i] * wv[j];
        }
        __syncthreads();
    }

#pragma unroll
    for (int i = 0; i < 8; i++) {
        size_t row = (size_t)(bm + ty * 8 + i);
#pragma unroll
        for (int j = 0; j < 8; j += 4) {
            int col = bn + tx * 8 + j;
            float4 v;
            v.x = acc[i][j + 0];
            v.y = acc[i][j + 1];
            v.z = acc[i][j + 2];
            v.w = acc[i][j + 3];
            if (bias != nullptr) {
                v.x += bias[col + 0];
                v.y += bias[col + 1];
                v.z += bias[col + 2];
                v.w += bias[col + 3];
            }
            *(float4*)(C + row * N + col) = v;
        }
    }
}

// ---------------------------------------------------------------------------
// Fused attention (flash-style, fp32): per block one (b, h, 64-row Q tile).
// Loops over 64-wide K/V tiles with online softmax. Mask honored as an
// additive bias staged in the P buffer (re-used: each thread reads exactly
// the cells it later overwrites with P).
// scores scaled by 1/sqrt(E)=1/32 (applied to Q at load; mask addend
// pre-scaled to -1e20/32).
// ---------------------------------------------------------------------------
#define BR 64
#define BC 64
#define KSTR 65   // pad stride for K/V/P (65 % 32 == 1 -> <=2-way conflicts)

#define ATTN_SMEM_BYTES ((BR * 64 + 3 * BC * KSTR) * 4)

__global__ __launch_bounds__(256) void attn_kernel(const int* __restrict__ mask) {
    extern __shared__ float sm[];
    float* Qs = sm;                    // [64][64]   (broadcast reads -> no pad)
    float* Ks = Qs + BR * 64;          // [64][65]
    float* Vs = Ks + BC * KSTR;        // [64][65]
    float* Ps = Vs + BC * KSTR;        // [64][65]  mask-addend, then P

    const int tid = threadIdx.x;
    const int bh = blockIdx.y;
    const int b = bh >> 4;     // / HH
    const int h = bh & 15;     // % HH
    const int q0 = blockIdx.x * BR;
    const int tx = tid & 15;
    const int ty = tid >> 4;
    const int r0 = ty * 4;
    const int c0 = tx * 4;

    const float scale = 0.03125f;            // 1/sqrt(1024)
    const float mask_addend = -3.125e18f;    // -1e20 * scale

    // Load Q tile (pre-scaled)
#pragma unroll
    for (int t = 0; t < 4; t++) {
        int f4 = tid + 256 * t;
        int row = f4 >> 4;
        int col = (f4 & 15) << 2;
        float4 q = *(const float4*)(g_q + (size_t)(b * LL + q0 + row) * EE + h * DD + col);
        Qs[row * 64 + col + 0] = q.x * scale;
        Qs[row * 64 + col + 1] = q.y * scale;
        Qs[row * 64 + col + 2] = q.z * scale;
        Qs[row * 64 + col + 3] = q.w * scale;
    }

    float o[4][4];
    float mrow[4], lrow[4];
#pragma unroll
    for (int i = 0; i < 4; i++) {
        mrow[i] = -1e30f;
        lrow[i] = 0.0f;
#pragma unroll
        for (int j = 0; j < 4; j++) o[i][j] = 0.0f;
    }

    const size_t mask_b = (size_t)b * LL * LL;

    for (int kt = 0; kt < LL / BC; kt++) {
        const int k0 = kt * BC;
        __syncthreads();   // protect Ks/Vs/Ps from previous iteration's readers

        // Cooperative load: K tile, V tile, mask tile (as pre-scaled addend)
#pragma unroll
        for (int t = 0; t < 4; t++) {
            int f4 = tid + 256 * t;
            int row = f4 >> 4;
            int col = (f4 & 15) << 2;
            size_t g = (size_t)(b * LL + k0 + row) * EE + h * DD + col;
            float4 kv = *(const float4*)(g_k + g);
            Ks[row * KSTR + col + 0] = kv.x;
            Ks[row * KSTR + col + 1] = kv.y;
            Ks[row * KSTR + col + 2] = kv.z;
            Ks[row * KSTR + col + 3] = kv.w;
            float4 vv = *(const float4*)(g_v + g);
            Vs[row * KSTR + col + 0] = vv.x;
            Vs[row * KSTR + col + 1] = vv.y;
            Vs[row * KSTR + col + 2] = vv.z;
            Vs[row * KSTR + col + 3] = vv.w;
            int4 mm = *(const int4*)(mask + mask_b + (size_t)(q0 + row) * LL + k0 + col);
            Ps[row * KSTR + col + 0] = (mm.x != 0) ? 0.0f : mask_addend;
            Ps[row * KSTR + col + 1] = (mm.y != 0) ? 0.0f : mask_addend;
            Ps[row * KSTR + col + 2] = (mm.z != 0) ? 0.0f : mask_addend;
            Ps[row * KSTR + col + 3] = (mm.w != 0) ? 0.0f : mask_addend;
        }
        __syncthreads();

        // S = Qs @ Ks^T + mask addend (4x4 per thread)
        float s[4][4];
#pragma unroll
        for (int i = 0; i < 4; i++)
#pragma unroll
            for (int j = 0; j < 4; j++)
                s[i][j] = Ps[(r0 + i) * KSTR + (c0 + j)];

#pragma unroll 16
        for (int d = 0; d < DD; d++) {
            float qv[4], kv[4];
#pragma unroll
            for (int i = 0; i < 4; i++) qv[i] = Qs[(r0 + i) * 64 + d];
#pragma unroll
            for (int j = 0; j < 4; j++) kv[j] = Ks[(c0 + j) * KSTR + d];
#pragma unroll
            for (int i = 0; i < 4; i++)
#pragma unroll
                for (int j = 0; j < 4; j++) s[i][j] += qv[i] * kv[j];
        }

        // Online softmax update per row (reduce across the 16 lanes sharing ty)
#pragma unroll
        for (int i = 0; i < 4; i++) {
            float mx = s[i][0];
#pragma unroll
            for (int j = 1; j < 4; j++) mx = fmaxf(mx, s[i][j]);
#pragma unroll
            for (int w = 8; w > 0; w >>= 1)
                mx = fmaxf(mx, __shfl_xor_sync(0xffffffffu, mx, w));
            float mnew = fmaxf(mrow[i], mx);
            float alpha = __expf(mrow[i] - mnew);
            mrow[i] = mnew;
            float psum = 0.0f;
#pragma unroll
            for (int j = 0; j < 4; j++) {
                s[i][j] = __expf(s[i][j] - mnew);
                psum += s[i][j];
            }
#pragma unroll
            for (int w = 8; w > 0; w >>= 1)
                psum += __shfl_xor_sync(0xffffffffu, psum, w);
            lrow[i] = lrow[i] * alpha + psum;
#pragma unroll
            for (int j = 0; j < 4; j++) {
                o[i][j] *= alpha;
                Ps[(r0 + i) * KSTR + (c0 + j)] = s[i][j];  // same cells we read
            }
        }
        __syncthreads();

        // O += P @ V  (4x4 per thread over full 64 inner dim)
#pragma unroll 8
        for (int c = 0; c < BC; c++) {
            float pv[4], vv[4];
#pragma unroll
            for (int i = 0; i < 4; i++) pv[i] = Ps[(r0 + i) * KSTR + c];
#pragma unroll
            for (int j = 0; j < 4; j++) vv[j] = Vs[c * KSTR + (c0 + j)];
#pragma unroll
            for (int i = 0; i < 4; i++)
#pragma unroll
                for (int j = 0; j < 4; j++) o[i][j] += pv[i] * vv[j];
        }
    }

    // Epilogue: normalize and write ctx[b, q, h*D + d]
#pragma unroll
    for (int i = 0; i < 4; i++) {
        float inv = 1.0f / lrow[i];
        size_t base = (size_t)(b * LL + q0 + r0 + i) * EE + h * DD + c0;
        float4 v;
        v.x = o[i][0] * inv;
        v.y = o[i][1] * inv;
        v.z = o[i][2] * inv;
        v.w = o[i][3] * inv;
        *(float4*)(g_ctx + base) = v;
    }
}

// ---------------------------------------------------------------------------
// Launch
// ---------------------------------------------------------------------------
extern "C" void kernel_launch(void* const* d_in, const int* in_sizes, int n_in,
                              void* d_out, int out_size) {
    const float* queries = (const float*)d_in[0];
    const float* keys    = (const float*)d_in[1];
    const float* values  = (const float*)d_in[2];
    const int*   mask    = (const int*)d_in[3];
    const float* Wq      = (const float*)d_in[4];
    const float* Wk      = (const float*)d_in[5];
    const float* Wv      = (const float*)d_in[6];
    const float* Wo      = (const float*)d_in[7];
    const float* bo      = (const float*)d_in[8];
    float* out = (float*)d_out;

    float *q, *k, *v, *ctx;
    cudaGetSymbolAddress((void**)&q,   g_q);
    cudaGetSymbolAddress((void**)&k,   g_k);
    cudaGetSymbolAddress((void**)&v,   g_v);
    cudaGetSymbolAddress((void**)&ctx, g_ctx);

    cudaFuncSetAttribute(attn_kernel, cudaFuncAttributeMaxDynamicSharedMemorySize,
                         ATTN_SMEM_BYTES);

    dim3 gg(ML / GTM, EE / GTN);   // 64 x 8
    sgemm_nt<<<gg, 256>>>(queries, Wq, nullptr, q, ML, EE, EE);
    sgemm_nt<<<gg, 256>>>(keys,    Wk, nullptr, k, ML, EE, EE);
    sgemm_nt<<<gg, 256>>>(values,  Wv, nullptr, v, ML, EE, EE);

    dim3 ga(LL / BR, BB * HH);     // 32 x 64
    attn_kernel<<<ga, 256, ATTN_SMEM_BYTES>>>(mask);

    sgemm_nt<<<gg, 256>>>(ctx, Wo, bo, out, ML, EE, EE);
}

// round 2
// speedup vs baseline: 1.0009x; 1.0009x over previous
#include <cuda_runtime.h>
#include <math.h>

// Problem constants
#define BB 4
#define LL 2048
#define EE 1024
#define HH 16
#define DD 64
#define ML (BB * LL)   // 8192 total rows

// Scratch (device globals: allocation-free per harness rules)
__device__ float g_q[ML * EE];
__device__ float g_k[ML * EE];
__device__ float g_v[ML * EE];
__device__ float g_ctx[ML * EE];

// ---------------------------------------------------------------------------
// SGEMM: C[M,N] = A[M,K] @ W[N,K]^T (+ bias[N])
// 128x128 block tile, K-tile 16, 256 threads, 8x8 per-thread microtile.
// ---------------------------------------------------------------------------
#define GTM 128
#define GTN 128
#define GTK 16
#define GPAD 4   // keeps rows 16B-aligned for float4 smem reads

__global__ __launch_bounds__(256) void sgemm_nt(const float* __restrict__ A,
                                                const float* __restrict__ W,
                                                const float* __restrict__ bias,
                                                float* __restrict__ C,
                                                int M, int N, int K) {
    __shared__ float As[GTK][GTM + GPAD];
    __shared__ float Ws[GTK][GTN + GPAD];

    const int tid = threadIdx.x;
    const int bm = blockIdx.x * GTM;
    const int bn = blockIdx.y * GTN;
    const int tx = tid & 15;
    const int ty = tid >> 4;
    const int lrow = tid >> 2;          // 0..63
    const int lcol = (tid & 3) << 2;    // 0,4,8,12

    float acc[8][8];
#pragma unroll
    for (int i = 0; i < 8; i++)
#pragma unroll
        for (int j = 0; j < 8; j++) acc[i][j] = 0.0f;

    for (int k0 = 0; k0 < K; k0 += GTK) {
#pragma unroll
        for (int hf = 0; hf < 2; hf++) {
            int r = lrow + hf * 64;
            float4 a = *(const float4*)(A + (size_t)(bm + r) * K + k0 + lcol);
            As[lcol + 0][r] = a.x;
            As[lcol + 1][r] = a.y;
            As[lcol + 2][r] = a.z;
            As[lcol + 3][r] = a.w;
            float4 w = *(const float4*)(W + (size_t)(bn + r) * K + k0 + lcol);
            Ws[lcol + 0][r] = w.x;
            Ws[lcol + 1][r] = w.y;
            Ws[lcol + 2][r] = w.z;
            Ws[lcol + 3][r] = w.w;
        }
        __syncthreads();

#pragma unroll
        for (int kk = 0; kk < GTK; kk++) {
            float4 a0 = *(const float4*)&As[kk][ty * 8];
            float4 a1 = *(const float4*)&As[kk][ty * 8 + 4];
            float4 w0 = *(const float4*)&Ws[kk][tx * 8];
            float4 w1 = *(const float4*)&Ws[kk][tx * 8 + 4];
            float av[8] = {a0.x, a0.y, a0.z, a0.w, a1.x, a1.y, a1.z, a1.w};
            float wv[8] = {w0.x, w0.y, w0.z, w0.w, w1.x, w1.y, w1.z, w1.w};
#pragma unroll
            for (int i = 0; i < 8; i++)
#pragma unroll
                for (int j = 0; j < 8; j++) acc[i][j] += av[i] * wv[j];
        }
        __syncthreads();
    }

#pragma unroll
    for (int i = 0; i < 8; i++) {
        size_t row = (size_t)(bm + ty * 8 + i);
#pragma unroll
        for (int j = 0; j < 8; j += 4) {
            int col = bn + tx * 8 + j;
            float4 v;
            v.x = acc[i][j + 0];
            v.y = acc[i][j + 1];
            v.z = acc[i][j + 2];
            v.w = acc[i][j + 3];
            if (bias != nullptr) {
                v.x += bias[col + 0];
                v.y += bias[col + 1];
                v.z += bias[col + 2];
                v.w += bias[col + 3];
            }
            *(float4*)(C + row * N + col) = v;
        }
    }
}

// ---------------------------------------------------------------------------
// Fused attention (flash-style, fp32): per block one (b, h, 64-row Q tile).
// Loops over 64-wide K/V tiles with online softmax. Mask honored as an
// additive bias staged in the P buffer (re-used: each thread reads exactly
// the cells it later overwrites with P).
// scores scaled by 1/sqrt(E)=1/32 (applied to Q at load; mask addend
// pre-scaled to -1e20/32).
// ---------------------------------------------------------------------------
#define BR 64
#define BC 64
#define KSTR 65   // pad stride for K/V/P (65 % 32 == 1 -> <=2-way conflicts)

#define ATTN_SMEM_BYTES ((BR * 64 + 3 * BC * KSTR) * 4)

__global__ __launch_bounds__(256) void attn_kernel(const int* __restrict__ mask) {
    extern __shared__ float sm[];
    float* Qs = sm;                    // [64][64]   (broadcast reads -> no pad)
    float* Ks = Qs + BR * 64;          // [64][65]
    float* Vs = Ks + BC * KSTR;        // [64][65]
    float* Ps = Vs + BC * KSTR;        // [64][65]  mask-addend, then P

    const int tid = threadIdx.x;
    const int bh = blockIdx.y;
    const int b = bh >> 4;     // / HH
    const int h = bh & 15;     // % HH
    const int q0 = blockIdx.x * BR;
    const int tx = tid & 15;
    const int ty = tid >> 4;
    const int r0 = ty * 4;
    const int c0 = tx * 4;

    const float scale = 0.03125f;            // 1/sqrt(1024)
    const float mask_addend = -3.125e18f;    // -1e20 * scale

    // Load Q tile (pre-scaled)
#pragma unroll
    for (int t = 0; t < 4; t++) {
        int f4 = tid + 256 * t;
        int row = f4 >> 4;
        int col = (f4 & 15) << 2;
        float4 q = *(const float4*)(g_q + (size_t)(b * LL + q0 + row) * EE + h * DD + col);
        Qs[row * 64 + col + 0] = q.x * scale;
        Qs[row * 64 + col + 1] = q.y * scale;
        Qs[row * 64 + col + 2] = q.z * scale;
        Qs[row * 64 + col + 3] = q.w * scale;
    }

    float o[4][4];
    float mrow[4], lrow[4];
#pragma unroll
    for (int i = 0; i < 4; i++) {
        mrow[i] = -1e30f;
        lrow[i] = 0.0f;
#pragma unroll
        for (int j = 0; j < 4; j++) o[i][j] = 0.0f;
    }

    const size_t mask_b = (size_t)b * LL * LL;

    for (int kt = 0; kt < LL / BC; kt++) {
        const int k0 = kt * BC;
        __syncthreads();   // protect Ks/Vs/Ps from previous iteration's readers

        // Cooperative load: K tile, V tile, mask tile (as pre-scaled addend)
#pragma unroll
        for (int t = 0; t < 4; t++) {
            int f4 = tid + 256 * t;
            int row = f4 >> 4;
            int col = (f4 & 15) << 2;
            size_t g = (size_t)(b * LL + k0 + row) * EE + h * DD + col;
            float4 kv = *(const float4*)(g_k + g);
            Ks[row * KSTR + col + 0] = kv.x;
            Ks[row * KSTR + col + 1] = kv.y;
            Ks[row * KSTR + col + 2] = kv.z;
            Ks[row * KSTR + col + 3] = kv.w;
            float4 vv = *(const float4*)(g_v + g);
            Vs[row * KSTR + col + 0] = vv.x;
            Vs[row * KSTR + col + 1] = vv.y;
            Vs[row * KSTR + col + 2] = vv.z;
            Vs[row * KSTR + col + 3] = vv.w;
            int4 mm = *(const int4*)(mask + mask_b + (size_t)(q0 + row) * LL + k0 + col);
            Ps[row * KSTR + col + 0] = (mm.x != 0) ? 0.0f : mask_addend;
            Ps[row * KSTR + col + 1] = (mm.y != 0) ? 0.0f : mask_addend;
            Ps[row * KSTR + col + 2] = (mm.z != 0) ? 0.0f : mask_addend;
            Ps[row * KSTR + col + 3] = (mm.w != 0) ? 0.0f : mask_addend;
        }
        __syncthreads();

        // S = Qs @ Ks^T + mask addend (4x4 per thread)
        float s[4][4];
#pragma unroll
        for (int i = 0; i < 4; i++)
#pragma unroll
            for (int j = 0; j < 4; j++)
                s[i][j] = Ps[(r0 + i) * KSTR + (c0 + j)];

#pragma unroll 16
        for (int d = 0; d < DD; d++) {
            float qv[4], kv[4];
#pragma unroll
            for (int i = 0; i < 4; i++) qv[i] = Qs[(r0 + i) * 64 + d];
#pragma unroll
            for (int j = 0; j < 4; j++) kv[j] = Ks[(c0 + j) * KSTR + d];
#pragma unroll
            for (int i = 0; i < 4; i++)
#pragma unroll
                for (int j = 0; j < 4; j++) s[i][j] += qv[i] * kv[j];
        }

        // Online softmax update per row (reduce across the 16 lanes sharing ty)
#pragma unroll
        for (int i = 0; i < 4; i++) {
            float mx = s[i][0];
#pragma unroll
            for (int j = 1; j < 4; j++) mx = fmaxf(mx, s[i][j]);
#pragma unroll
            for (int w = 8; w > 0; w >>= 1)
                mx = fmaxf(mx, __shfl_xor_sync(0xffffffffu, mx, w));
            float mnew = fmaxf(mrow[i], mx);
            float alpha = __expf(mrow[i] - mnew);
            mrow[i] = mnew;
            float psum = 0.0f;
#pragma unroll
            for (int j = 0; j < 4; j++) {
                s[i][j] = __expf(s[i][j] - mnew);
                psum += s[i][j];
            }
#pragma unroll
            for (int w = 8; w > 0; w >>= 1)
                psum += __shfl_xor_sync(0xffffffffu, psum, w);
            lrow[i] = lrow[i] * alpha + psum;
#pragma unroll
            for (int j = 0; j < 4; j++) {
                o[i][j] *= alpha;
                Ps[(r0 + i) * KSTR + (c0 + j)] = s[i][j];  // same cells we read
            }
        }
        __syncthreads();

        // O += P @ V  (4x4 per thread over full 64 inner dim)
#pragma unroll 8
        for (int c = 0; c < BC; c++) {
            float pv[4], vv[4];
#pragma unroll
            for (int i = 0; i < 4; i++) pv[i] = Ps[(r0 + i) * KSTR + c];
#pragma unroll
            for (int j = 0; j < 4; j++) vv[j] = Vs[c * KSTR + (c0 + j)];
#pragma unroll
            for (int i = 0; i < 4; i++)
#pragma unroll
                for (int j = 0; j < 4; j++) o[i][j] += pv[i] * vv[j];
        }
    }

    // Epilogue: normalize and write ctx[b, q, h*D + d]
#pragma unroll
    for (int i = 0; i < 4; i++) {
        float inv = 1.0f / lrow[i];
        size_t base = (size_t)(b * LL + q0 + r0 + i) * EE + h * DD + c0;
        float4 v;
        v.x = o[i][0] * inv;
        v.y = o[i][1] * inv;
        v.z = o[i][2] * inv;
        v.w = o[i][3] * inv;
        *(float4*)(g_ctx + base) = v;
    }
}

// ---------------------------------------------------------------------------
// Launch
// ---------------------------------------------------------------------------
extern "C" void kernel_launch(void* const* d_in, const int* in_sizes, int n_in,
                              void* d_out, int out_size) {
    const float* queries = (const float*)d_in[0];
    const float* keys    = (const float*)d_in[1];
    const float* values  = (const float*)d_in[2];
    const int*   mask    = (const int*)d_in[3];
    const float* Wq      = (const float*)d_in[4];
    const float* Wk      = (const float*)d_in[5];
    const float* Wv      = (const float*)d_in[6];
    const float* Wo      = (const float*)d_in[7];
    const float* bo      = (const float*)d_in[8];
    float* out = (float*)d_out;

    float *q, *k, *v, *ctx;
    cudaGetSymbolAddress((void**)&q,   g_q);
    cudaGetSymbolAddress((void**)&k,   g_k);
    cudaGetSymbolAddress((void**)&v,   g_v);
    cudaGetSymbolAddress((void**)&ctx, g_ctx);

    cudaFuncSetAttribute(attn_kernel, cudaFuncAttributeMaxDynamicSharedMemorySize,
                         ATTN_SMEM_BYTES);

    dim3 gg(ML / GTM, EE / GTN);   // 64 x 8
    sgemm_nt<<<gg, 256>>>(queries, Wq, nullptr, q, ML, EE, EE);
    sgemm_nt<<<gg, 256>>>(keys,    Wk, nullptr, k, ML, EE, EE);
    sgemm_nt<<<gg, 256>>>(values,  Wv, nullptr, v, ML, EE, EE);

    dim3 ga(LL / BR, BB * HH);     // 32 x 64
    attn_kernel<<<ga, 256, ATTN_SMEM_BYTES>>>(mask);

    sgemm_nt<<<gg, 256>>>(ctx, Wo, bo, out, ML, EE, EE);
}